// round 7
// baseline (speedup 1.0000x reference)
#include <cuda_runtime.h>
#include <cuda_bf16.h>
#include <cuda_fp16.h>
#include <cstdint>

#define NNODES 100000
#define NEDGES 1600000
#define FIN 128
#define FHID 128
#define FOUT 64

// ---------------- scratch (static device globals; no allocation) ----------------
__device__ __half   g_Xh [(size_t)3 * NNODES * FIN];   // fp16 copy of nsrc*feat
__device__ uint32_t g_XSh[(size_t)3 * NNODES * 64];    // XS bf16-hi plane (k-pairs packed)
__device__ uint32_t g_XSl[(size_t)3 * NNODES * 64];    // XS bf16-lo plane
__device__ __half   g_H2 [(size_t)3 * NNODES * FOUT];  // layer-2 transformed features (fp16)
__device__ int      g_cnt     [3 * NNODES];
__device__ int      g_outcnt  [3 * NNODES];
__device__ int      g_rowstart[3 * (NNODES + 1)];
__device__ int      g_esrc    [3 * NEDGES];
__device__ float    g_nsrc    [3 * NNODES];
__device__ float    g_ndst    [3 * NNODES];
__device__ uint32_t g_W1h[64 * 128], g_W1l[64 * 128];  // W1 packed bf16 hi/lo (k-pairs)
__device__ uint32_t g_W2h[64 * 64],  g_W2l[64 * 64];   // W2 packed bf16 hi/lo

struct F3 { const float* p[3]; };
struct I3 { const int*   p[3]; };

// ---------------- bf16 split helpers ----------------
__device__ __forceinline__ void split2(float f0, float f1, uint32_t& uh, uint32_t& ul) {
    __nv_bfloat16 h0 = __float2bfloat16_rn(f0), h1 = __float2bfloat16_rn(f1);
    float r0 = f0 - __bfloat162float(h0);
    float r1 = f1 - __bfloat162float(h1);
    __nv_bfloat16 l0 = __float2bfloat16_rn(r0), l1 = __float2bfloat16_rn(r1);
    uh = ((uint32_t)(*(uint16_t*)&h1) << 16) | (uint32_t)(*(uint16_t*)&h0);
    ul = ((uint32_t)(*(uint16_t*)&l1) << 16) | (uint32_t)(*(uint16_t*)&l0);
}

__device__ __forceinline__ void mma_bf16(float* d, const uint32_t* a, const uint32_t* b) {
    asm volatile(
        "mma.sync.aligned.m16n8k16.row.col.f32.bf16.bf16.f32 "
        "{%0,%1,%2,%3},{%4,%5,%6,%7},{%8,%9},{%0,%1,%2,%3};"
        : "+f"(d[0]), "+f"(d[1]), "+f"(d[2]), "+f"(d[3])
        : "r"(a[0]), "r"(a[1]), "r"(a[2]), "r"(a[3]), "r"(b[0]), "r"(b[1]));
}

// ---------------- launch 0: zero histograms + pack weights ----------------
__global__ void zero_pack(int* cnt, int* outcnt,
                          const float* __restrict__ W1, const float* __restrict__ W2,
                          uint32_t* w1h, uint32_t* w1l, uint32_t* w2h, uint32_t* w2l) {
    int i = blockIdx.x * blockDim.x + threadIdx.x;
    if (i < 3 * NNODES) { cnt[i] = 0; outcnt[i] = 0; }
    if (i < 64 * 128) {
        int kp = i >> 7, c = i & 127;
        split2(W1[(2 * kp) * FHID + c], W1[(2 * kp + 1) * FHID + c], w1h[i], w1l[i]);
    }
    if (i < 64 * 64) {
        int kp = i >> 6, c = i & 63;
        split2(W2[(2 * kp) * FOUT + c], W2[(2 * kp + 1) * FOUT + c], w2h[i], w2l[i]);
    }
}

// ---------------- launch 1: degree histograms ----------------
__global__ void hist_all(I3 srcs, I3 dsts, int* cnt, int* outcnt) {
    int g = blockIdx.y;
    int e = blockIdx.x * blockDim.x + threadIdx.x;
    if (e < NEDGES) {
        atomicAdd(&cnt   [g * NNODES + dsts.p[g][e]], 1);
        atomicAdd(&outcnt[g * NNODES + srcs.p[g][e]], 1);
    }
}

// ---------------- launch 2: exclusive scan + norms (one block per graph) ----------------
__global__ void scan_norms(int* __restrict__ cntAll,
                           const int* __restrict__ outcntAll,
                           int* __restrict__ rowstartAll,
                           float* __restrict__ nsrcAll,
                           float* __restrict__ ndstAll) {
    __shared__ int part[1024];
    const int gb = blockIdx.x;
    int* cnt      = cntAll      + gb * NNODES;
    const int* outcnt = outcntAll + gb * NNODES;
    int* rowstart = rowstartAll + gb * (NNODES + 1);
    float* nsrc   = nsrcAll + gb * NNODES;
    float* ndst   = ndstAll + gb * NNODES;
    const int t = threadIdx.x;
    const int chunk = (NNODES + 1023) / 1024;
    const int lo = t * chunk;
    const int hi = min(lo + chunk, NNODES);
    int s = 0;
    for (int i = lo; i < hi; i++) {
        int c = cnt[i];
        s += c;
        ndst[i] = rsqrtf(fmaxf((float)c, 1.f));
        nsrc[i] = rsqrtf(fmaxf((float)outcnt[i], 1.f));
    }
    part[t] = s;
    __syncthreads();
    for (int off = 1; off < 1024; off <<= 1) {
        int v = (t >= off) ? part[t - off] : 0;
        __syncthreads();
        part[t] += v;
        __syncthreads();
    }
    int run = part[t] - s;
    for (int i = lo; i < hi; i++) {
        rowstart[i] = run;
        run += cnt[i];
        cnt[i] = 0;
    }
    if (t == 1023) rowstart[NNODES] = part[1023];
}

// ---------------- launch 3: CSR fill (ncu capture slot) ----------------
__global__ void fill_all(I3 srcs, I3 dsts, const int* __restrict__ rowstartAll,
                         int* cnt, int* __restrict__ esrcAll) {
    int g = blockIdx.y;
    int e = blockIdx.x * blockDim.x + threadIdx.x;
    if (e < NEDGES) {
        int d = dsts.p[g][e];
        int pos = rowstartAll[g * (NNODES + 1) + d] + atomicAdd(&cnt[g * NNODES + d], 1);
        esrcAll[g * NEDGES + pos] = srcs.p[g][e];
    }
}

// ---------------- launch 4: fp16 scaled feature copy ----------------
// Xh[g][node][c] = fp16(nsrc[node] * feat[node][c])
__global__ __launch_bounds__(256)
void convert_feat(F3 feats, const float* __restrict__ nsrcAll,
                  __half* __restrict__ XhBase) {
    const int PER_G = NNODES * (FIN / 2);    // half2 pairs per graph
    int i = blockIdx.x * blockDim.x + threadIdx.x;
    if (i >= 3 * PER_G) return;
    int g = i / PER_G;
    int rem = i - g * PER_G;
    int node = rem >> 6;          // FIN/2 = 64 pairs per node
    int c    = rem & 63;
    float2 v = __ldg((const float2*)(feats.p[g] + (size_t)node * FIN) + c);
    float s  = __ldg(nsrcAll + g * NNODES + node);
    half2 h = __floats2half2_rn(v.x * s, v.y * s);
    ((half2*)(XhBase + (size_t)g * NNODES * FIN))[rem] = h;
}

// ---------------- launch 5: scaled gather SpMM (fp16 rows, fp32 accumulate) ----------------
// XS[i,:] = sum_{e in row i} Xh[esrc[e],:]   -> packed bf16 hi/lo planes
__global__ __launch_bounds__(256)
void spmm_scaled(const __half* __restrict__ XhBase,
                 const int* __restrict__ rowstartAll,
                 const int* __restrict__ esrcAll,
                 uint32_t* __restrict__ XShBase,
                 uint32_t* __restrict__ XSlBase)
{
    const int gidx = blockIdx.y;
    const __half* X = XhBase + (size_t)gidx * NNODES * FIN;
    const int* rowstart = rowstartAll + gidx * (NNODES + 1);
    const int* esrc = esrcAll + (size_t)gidx * NEDGES;
    uint32_t* XSh = XShBase + (size_t)gidx * NNODES * 64;
    uint32_t* XSl = XSlBase + (size_t)gidx * NNODES * 64;

    int gt = blockIdx.x * blockDim.x + threadIdx.x;
    int row = gt >> 5;        // warp id == row
    int lc  = gt & 31;        // uint2 lane: 4 halves each (32 x 4 = 128 cols)
    if (row >= NNODES) return;

    int beg = rowstart[row];
    int end = rowstart[row + 1];
    float4 acc = make_float4(0.f, 0.f, 0.f, 0.f);
    int e = beg;
    for (; e + 4 <= end; e += 4) {
        int s0 = __ldg(esrc + e + 0);
        int s1 = __ldg(esrc + e + 1);
        int s2 = __ldg(esrc + e + 2);
        int s3 = __ldg(esrc + e + 3);
        uint2 u0 = __ldg((const uint2*)(X + (size_t)s0 * FIN) + lc);
        uint2 u1 = __ldg((const uint2*)(X + (size_t)s1 * FIN) + lc);
        uint2 u2 = __ldg((const uint2*)(X + (size_t)s2 * FIN) + lc);
        uint2 u3 = __ldg((const uint2*)(X + (size_t)s3 * FIN) + lc);
#pragma unroll
        for (int j = 0; j < 4; j++) {
            uint2 u = (j == 0) ? u0 : (j == 1) ? u1 : (j == 2) ? u2 : u3;
            float2 fa = __half22float2(*(half2*)&u.x);
            float2 fb = __half22float2(*(half2*)&u.y);
            acc.x += fa.x; acc.y += fa.y; acc.z += fb.x; acc.w += fb.y;
        }
    }
    for (; e < end; e++) {
        int s = __ldg(esrc + e);
        uint2 u = __ldg((const uint2*)(X + (size_t)s * FIN) + lc);
        float2 fa = __half22float2(*(half2*)&u.x);
        float2 fb = __half22float2(*(half2*)&u.y);
        acc.x += fa.x; acc.y += fa.y; acc.z += fb.x; acc.w += fb.y;
    }
    // pack to bf16 hi/lo planes (k-pair packed: word j covers cols 2j,2j+1)
    uint32_t h0, l0, h1, l1;
    split2(acc.x, acc.y, h0, l0);
    split2(acc.z, acc.w, h1, l1);
    *((uint2*)(XSh + (size_t)row * 64) + lc) = make_uint2(h0, h1);
    *((uint2*)(XSl + (size_t)row * 64) + lc) = make_uint2(l0, l1);
}

// ---------------- launch 6: fused dense chain ----------------
// H2 = fp16( relu( (XS @ W1) * ndst + b1 ) @ W2 * nsrc )
#define LDAp 12
#define LDB1 136
#define LDT  68
#define LDB2 72
#define OFF_AH 0
#define OFF_AL (OFF_AH + 128 * LDAp)
#define OFF_B1H (OFF_AL + 128 * LDAp)
#define OFF_B1L (OFF_B1H + 8 * LDB1)
#define OFF_TH (OFF_B1L + 8 * LDB1)
#define OFF_TL (OFF_TH + 128 * LDT)
#define OFF_B2H (OFF_TL + 128 * LDT)
#define OFF_B2L (OFF_B2H + 8 * LDB2)
#define OFF_BSH (OFF_B2L + 8 * LDB2)
#define SMEM_WORDS (OFF_BSH + 128)

__global__ __launch_bounds__(256)
void fused_gemm(const uint32_t* __restrict__ XShBase,
                const uint32_t* __restrict__ XSlBase,
                const uint32_t* __restrict__ W1h, const uint32_t* __restrict__ W1l,
                const uint32_t* __restrict__ W2h, const uint32_t* __restrict__ W2l,
                const float* __restrict__ b1,
                __half* __restrict__ H2base,
                const float* __restrict__ nsrcAll,
                const float* __restrict__ ndstAll)
{
    extern __shared__ uint32_t sm[];
    uint32_t* Ahp = sm + OFF_AH;    // [128][LDAp]
    uint32_t* Alp = sm + OFF_AL;
    uint32_t* B1h = sm + OFF_B1H;   // [8][LDB1]
    uint32_t* B1l = sm + OFF_B1L;
    uint32_t* Th  = sm + OFF_TH;    // [128][LDT]
    uint32_t* Tl  = sm + OFF_TL;
    uint32_t* B2h = sm + OFF_B2H;   // [8][LDB2]
    uint32_t* B2l = sm + OFF_B2L;
    float*    bsh = (float*)(sm + OFF_BSH);

    const int gidx = blockIdx.y;
    const uint32_t* XSh = XShBase + (size_t)gidx * NNODES * 64;
    const uint32_t* XSl = XSlBase + (size_t)gidx * NNODES * 64;
    __half*      H2   = H2base + (size_t)gidx * NNODES * FOUT;
    const float* nsrc = nsrcAll + gidx * NNODES;
    const float* ndst = ndstAll + gidx * NNODES;

    const int tid  = threadIdx.x;
    const int warp = tid >> 5;
    const int lane = tid & 31;
    const int warp_m = warp & 3;
    const int warp_n = warp >> 2;
    const int m0w = warp_m * 32;
    const int g  = lane >> 2;
    const int tg = lane & 3;
    const int blockRow = blockIdx.x * 128;
    const int M = NNODES;

    if (tid < FHID) bsh[tid] = b1[tid];

    // ================= stage 1: T = XS @ W1 (3-term bf16) =================
    float acc1[2][8][4];
#pragma unroll
    for (int mi = 0; mi < 2; mi++)
#pragma unroll
        for (int ni = 0; ni < 8; ni++)
#pragma unroll
            for (int j = 0; j < 4; j++) acc1[mi][ni][j] = 0.f;

    const int n0w1 = warp_n * 64;
    const int arow = tid >> 1;          // 0..127
    const int aq   = (tid & 1) * 4;     // uint4 column within 8-wide chunk

    for (int kc = 0; kc < FIN; kc += 16) {
        __syncthreads();
        // A chunk: pre-packed planes, direct copy
        {
            int grow = blockRow + arow;
            uint4 vh = make_uint4(0u, 0u, 0u, 0u);
            uint4 vl = make_uint4(0u, 0u, 0u, 0u);
            if (grow < M) {
                vh = *(const uint4*)(XSh + (size_t)grow * 64 + kc / 2 + aq);
                vl = *(const uint4*)(XSl + (size_t)grow * 64 + kc / 2 + aq);
            }
            *(uint4*)&Ahp[arow * LDAp + aq] = vh;
            *(uint4*)&Alp[arow * LDAp + aq] = vl;
        }
        // B1 chunk (pre-packed)
        {
            int jp = tid >> 5;
            int c4 = (tid & 31) * 4;
            *(uint4*)&B1h[jp * LDB1 + c4] =
                *(const uint4*)(W1h + (size_t)(kc / 2 + jp) * FHID + c4);
            *(uint4*)&B1l[jp * LDB1 + c4] =
                *(const uint4*)(W1l + (size_t)(kc / 2 + jp) * FHID + c4);
        }
        __syncthreads();

        uint32_t ah[2][4], al[2][4];
#pragma unroll
        for (int mi = 0; mi < 2; mi++) {
            int r = m0w + mi * 16 + g;
            ah[mi][0] = Ahp[r * LDAp + tg];            al[mi][0] = Alp[r * LDAp + tg];
            ah[mi][1] = Ahp[(r + 8) * LDAp + tg];      al[mi][1] = Alp[(r + 8) * LDAp + tg];
            ah[mi][2] = Ahp[r * LDAp + tg + 4];        al[mi][2] = Alp[r * LDAp + tg + 4];
            ah[mi][3] = Ahp[(r + 8) * LDAp + tg + 4];  al[mi][3] = Alp[(r + 8) * LDAp + tg + 4];
        }
#pragma unroll
        for (int ni = 0; ni < 8; ni++) {
            int c = n0w1 + ni * 8 + g;
            uint32_t bh[2], bl[2];
            bh[0] = B1h[tg * LDB1 + c];        bl[0] = B1l[tg * LDB1 + c];
            bh[1] = B1h[(tg + 4) * LDB1 + c];  bl[1] = B1l[(tg + 4) * LDB1 + c];
#pragma unroll
            for (int mi = 0; mi < 2; mi++) {
                mma_bf16(acc1[mi][ni], al[mi], bh);
                mma_bf16(acc1[mi][ni], ah[mi], bl);
                mma_bf16(acc1[mi][ni], ah[mi], bh);
            }
        }
    }

    // ---- t = relu(T*ndst + b1), packed bf16 hi/lo into smem ----
    __syncthreads();
#pragma unroll
    for (int mi = 0; mi < 2; mi++) {
        int r0 = m0w + mi * 16 + g;
        int r1 = r0 + 8;
        int gr0 = blockRow + r0, gr1 = blockRow + r1;
        float nd0 = (gr0 < M) ? ndst[gr0] : 0.f;
        float nd1 = (gr1 < M) ? ndst[gr1] : 0.f;
#pragma unroll
        for (int ni = 0; ni < 8; ni++) {
            int col = n0w1 + ni * 8 + 2 * tg;
            int cp  = col >> 1;
            float t00 = fmaxf(fmaf(acc1[mi][ni][0], nd0, bsh[col]), 0.f);
            float t01 = fmaxf(fmaf(acc1[mi][ni][1], nd0, bsh[col + 1]), 0.f);
            float t10 = fmaxf(fmaf(acc1[mi][ni][2], nd1, bsh[col]), 0.f);
            float t11 = fmaxf(fmaf(acc1[mi][ni][3], nd1, bsh[col + 1]), 0.f);
            uint32_t h, l;
            split2(t00, t01, h, l);
            Th[r0 * LDT + cp] = h;  Tl[r0 * LDT + cp] = l;
            split2(t10, t11, h, l);
            Th[r1 * LDT + cp] = h;  Tl[r1 * LDT + cp] = l;
        }
    }

    // ================= stage 2: H2 = t @ W2 * nsrc =================
    float acc2[2][4][4];
#pragma unroll
    for (int mi = 0; mi < 2; mi++)
#pragma unroll
        for (int ni = 0; ni < 4; ni++)
#pragma unroll
            for (int j = 0; j < 4; j++) acc2[mi][ni][j] = 0.f;

    const int n0w2 = warp_n * 32;

    for (int ch = 0; ch < 8; ch++) {
        __syncthreads();
        if (tid < 128) {
            int jp = tid >> 4;
            int c4 = (tid & 15) * 4;
            *(uint4*)&B2h[jp * LDB2 + c4] =
                *(const uint4*)(W2h + (size_t)(ch * 8 + jp) * FOUT + c4);
        } else {
            int t2 = tid - 128;
            int jp = t2 >> 4;
            int c4 = (t2 & 15) * 4;
            *(uint4*)&B2l[jp * LDB2 + c4] =
                *(const uint4*)(W2l + (size_t)(ch * 8 + jp) * FOUT + c4);
        }
        __syncthreads();

        int cb = ch * 8;
        uint32_t ah[2][4], al[2][4];
#pragma unroll
        for (int mi = 0; mi < 2; mi++) {
            int r = m0w + mi * 16 + g;
            ah[mi][0] = Th[r * LDT + cb + tg];            al[mi][0] = Tl[r * LDT + cb + tg];
            ah[mi][1] = Th[(r + 8) * LDT + cb + tg];      al[mi][1] = Tl[(r + 8) * LDT + cb + tg];
            ah[mi][2] = Th[r * LDT + cb + tg + 4];        al[mi][2] = Tl[r * LDT + cb + tg + 4];
            ah[mi][3] = Th[(r + 8) * LDT + cb + tg + 4];  al[mi][3] = Tl[(r + 8) * LDT + cb + tg + 4];
        }
#pragma unroll
        for (int ni = 0; ni < 4; ni++) {
            int c = n0w2 + ni * 8 + g;
            uint32_t bh[2], bl[2];
            bh[0] = B2h[tg * LDB2 + c];        bl[0] = B2l[tg * LDB2 + c];
            bh[1] = B2h[(tg + 4) * LDB2 + c];  bl[1] = B2l[(tg + 4) * LDB2 + c];
#pragma unroll
            for (int mi = 0; mi < 2; mi++) {
                mma_bf16(acc2[mi][ni], al[mi], bh);
                mma_bf16(acc2[mi][ni], ah[mi], bl);
                mma_bf16(acc2[mi][ni], ah[mi], bh);
            }
        }
    }

    // ---- epilogue: H2 = fp16(acc2 * nsrc) ----
#pragma unroll
    for (int mi = 0; mi < 2; mi++) {
        int gr0 = blockRow + m0w + mi * 16 + g;
        int gr1 = gr0 + 8;
        float s0 = (gr0 < M) ? nsrc[gr0] : 0.f;
        float s1 = (gr1 < M) ? nsrc[gr1] : 0.f;
#pragma unroll
        for (int ni = 0; ni < 4; ni++) {
            int col = n0w2 + ni * 8 + 2 * tg;
            if (gr0 < M)
                *(half2*)(H2 + (size_t)gr0 * FOUT + col) =
                    __floats2half2_rn(acc2[mi][ni][0] * s0, acc2[mi][ni][1] * s0);
            if (gr1 < M)
                *(half2*)(H2 + (size_t)gr1 * FOUT + col) =
                    __floats2half2_rn(acc2[mi][ni][2] * s1, acc2[mi][ni][3] * s1);
        }
    }
}

// ---------------- launch 7: final gather SpMM (fp16 rows) ----------------
__global__ __launch_bounds__(256)
void spmm_out(const __half* __restrict__ H2base,
              const int* __restrict__ rowstartAll,
              const int* __restrict__ esrcAll,
              float* __restrict__ outBase,
              const float* __restrict__ ndstAll,
              const float* __restrict__ bias)
{
    constexpr int C = FOUT;          // 64 halves per row
    constexpr int CU2 = C / 4;       // 16 uint2 lanes per row
    const int gidx = blockIdx.y;
    const __half* H = H2base + (size_t)gidx * NNODES * C;
    const int* rowstart = rowstartAll + gidx * (NNODES + 1);
    const int* esrc = esrcAll + (size_t)gidx * NEDGES;
    float* out = outBase + (size_t)gidx * NNODES * C;

    int gt = blockIdx.x * blockDim.x + threadIdx.x;
    int w = gt >> 5;
    int lane = gt & 31;
    int sub = lane >> 4;             // 2 rows per warp
    int lc  = lane & 15;             // uint2 lane: 4 halves
    int row = w * 2 + sub;
    if (row >= NNODES) return;

    int beg = rowstart[row];
    int end = rowstart[row + 1];
    float4 acc = make_float4(0.f, 0.f, 0.f, 0.f);
    int e = beg;
    for (; e + 4 <= end; e += 4) {
        int s0 = __ldg(esrc + e + 0);
        int s1 = __ldg(esrc + e + 1);
        int s2 = __ldg(esrc + e + 2);
        int s3 = __ldg(esrc + e + 3);
        uint2 u0 = __ldg((const uint2*)(H + (size_t)s0 * C) + lc);
        uint2 u1 = __ldg((const uint2*)(H + (size_t)s1 * C) + lc);
        uint2 u2 = __ldg((const uint2*)(H + (size_t)s2 * C) + lc);
        uint2 u3 = __ldg((const uint2*)(H + (size_t)s3 * C) + lc);
#pragma unroll
        for (int j = 0; j < 4; j++) {
            uint2 u = (j == 0) ? u0 : (j == 1) ? u1 : (j == 2) ? u2 : u3;
            float2 fa = __half22float2(*(half2*)&u.x);
            float2 fb = __half22float2(*(half2*)&u.y);
            acc.x += fa.x; acc.y += fa.y; acc.z += fb.x; acc.w += fb.y;
        }
    }
    for (; e < end; e++) {
        int s = __ldg(esrc + e);
        uint2 u = __ldg((const uint2*)(H + (size_t)s * C) + lc);
        float2 fa = __half22float2(*(half2*)&u.x);
        float2 fb = __half22float2(*(half2*)&u.y);
        acc.x += fa.x; acc.y += fa.y; acc.z += fb.x; acc.w += fb.y;
    }
    float nd = ndstAll[gidx * NNODES + row];
    float4 b = ((const float4*)bias)[lc];
    acc.x = fmaf(acc.x, nd, b.x);
    acc.y = fmaf(acc.y, nd, b.y);
    acc.z = fmaf(acc.z, nd, b.z);
    acc.w = fmaf(acc.w, nd, b.w);
    *((float4*)(out + (size_t)row * C) + lc) = acc;
}

// ---------------- launch ----------------
extern "C" void kernel_launch(void* const* d_in, const int* in_sizes, int n_in,
                              void* d_out, int out_size)
{
    float *nsrc, *ndst;
    int *cnt, *outcnt, *rowstart, *esrc;
    uint32_t *xsh, *xsl, *w1h, *w1l, *w2h, *w2l;
    __half *xh, *h2;
    cudaGetSymbolAddress((void**)&xh,       g_Xh);
    cudaGetSymbolAddress((void**)&xsh,      g_XSh);
    cudaGetSymbolAddress((void**)&xsl,      g_XSl);
    cudaGetSymbolAddress((void**)&h2,       g_H2);
    cudaGetSymbolAddress((void**)&cnt,      g_cnt);
    cudaGetSymbolAddress((void**)&outcnt,   g_outcnt);
    cudaGetSymbolAddress((void**)&rowstart, g_rowstart);
    cudaGetSymbolAddress((void**)&esrc,     g_esrc);
    cudaGetSymbolAddress((void**)&nsrc,     g_nsrc);
    cudaGetSymbolAddress((void**)&ndst,     g_ndst);
    cudaGetSymbolAddress((void**)&w1h,      g_W1h);
    cudaGetSymbolAddress((void**)&w1l,      g_W1l);
    cudaGetSymbolAddress((void**)&w2h,      g_W2h);
    cudaGetSymbolAddress((void**)&w2l,      g_W2l);

    F3 feats = {{ (const float*)d_in[0], (const float*)d_in[3], (const float*)d_in[6] }};
    I3 srcs  = {{ (const int*)d_in[1],   (const int*)d_in[4],   (const int*)d_in[7] }};
    I3 dsts  = {{ (const int*)d_in[2],   (const int*)d_in[5],   (const int*)d_in[8] }};
    const float* W1 = (const float*)d_in[9];
    const float* b1 = (const float*)d_in[10];
    const float* W2 = (const float*)d_in[11];
    const float* b2 = (const float*)d_in[12];

    static const size_t SMEM_BYTES = SMEM_WORDS * sizeof(uint32_t);
    cudaFuncSetAttribute(fused_gemm, cudaFuncAttributeMaxDynamicSharedMemorySize,
                         (int)SMEM_BYTES);

    dim3 gE((NEDGES + 255) / 256, 3);
    dim3 gG((NNODES + 127) / 128, 3);
    dim3 gS1((NNODES * 32 + 255) / 256, 3);
    dim3 gS2((NNODES * 16 + 255) / 256, 3);
    const int CONV_BLOCKS = (3 * NNODES * (FIN / 2) + 255) / 256;

    zero_pack <<<(3 * NNODES + 255) / 256, 256>>>(cnt, outcnt, W1, W2, w1h, w1l, w2h, w2l);
    hist_all  <<<gE, 256>>>(srcs, dsts, cnt, outcnt);
    scan_norms<<<3, 1024>>>(cnt, outcnt, rowstart, nsrc, ndst);
    fill_all  <<<gE, 256>>>(srcs, dsts, rowstart, cnt, esrc);   // <- ncu capture slot (idx 3)
    convert_feat<<<CONV_BLOCKS, 256>>>(feats, nsrc, xh);

    // XS = gather(Xh), packed bf16 hi/lo planes
    spmm_scaled<<<gS1, 256>>>(xh, rowstart, esrc, xsh, xsl);
    // H2 = fp16( relu((XS@W1)*ndst + b1) @ W2 * nsrc )
    fused_gemm<<<gG, 256, SMEM_BYTES>>>(xsh, xsl, w1h, w1l, w2h, w2l, b1, h2, nsrc, ndst);
    // out = gather(H2)*ndst + b2
    spmm_out<<<gS2, 256>>>(h2, rowstart, esrc, (float*)d_out, ndst, b2);
}

// round 8
// speedup vs baseline: 1.2468x; 1.2468x over previous
#include <cuda_runtime.h>
#include <cuda_bf16.h>
#include <cstdint>

#define NNODES 100000
#define NEDGES 1600000
#define FIN 128
#define FHID 128
#define FOUT 64

// ---------------- scratch (static device globals; no allocation) ----------------
__device__ uint32_t g_XSh[(size_t)3 * NNODES * 64];    // XS bf16-hi plane (k-pairs packed)
__device__ uint32_t g_XSl[(size_t)3 * NNODES * 64];    // XS bf16-lo plane
__device__ float    g_H2 [(size_t)3 * NNODES * FOUT];  // layer-2 transformed features
__device__ int      g_cnt     [3 * NNODES];            // cursor (holds rowstart after scan)
__device__ int      g_outcnt  [3 * NNODES];
__device__ int      g_rowstart[3 * (NNODES + 1)];
__device__ int      g_esrc    [3 * NEDGES];
__device__ float    g_nsrc    [3 * NNODES];
__device__ float    g_ndst    [3 * NNODES];
__device__ uint32_t g_W1h[64 * 128], g_W1l[64 * 128];  // W1 packed bf16 hi/lo (k-pairs)
__device__ uint32_t g_W2h[64 * 64],  g_W2l[64 * 64];   // W2 packed bf16 hi/lo

struct F3 { const float* p[3]; };
struct I3 { const int*   p[3]; };

// ---------------- bf16 split helpers ----------------
__device__ __forceinline__ void split2(float f0, float f1, uint32_t& uh, uint32_t& ul) {
    __nv_bfloat16 h0 = __float2bfloat16_rn(f0), h1 = __float2bfloat16_rn(f1);
    float r0 = f0 - __bfloat162float(h0);
    float r1 = f1 - __bfloat162float(h1);
    __nv_bfloat16 l0 = __float2bfloat16_rn(r0), l1 = __float2bfloat16_rn(r1);
    uh = ((uint32_t)(*(uint16_t*)&h1) << 16) | (uint32_t)(*(uint16_t*)&h0);
    ul = ((uint32_t)(*(uint16_t*)&l1) << 16) | (uint32_t)(*(uint16_t*)&l0);
}

__device__ __forceinline__ void mma_bf16(float* d, const uint32_t* a, const uint32_t* b) {
    asm volatile(
        "mma.sync.aligned.m16n8k16.row.col.f32.bf16.bf16.f32 "
        "{%0,%1,%2,%3},{%4,%5,%6,%7},{%8,%9},{%0,%1,%2,%3};"
        : "+f"(d[0]), "+f"(d[1]), "+f"(d[2]), "+f"(d[3])
        : "r"(a[0]), "r"(a[1]), "r"(a[2]), "r"(a[3]), "r"(b[0]), "r"(b[1]));
}

// ---------------- launch 0: zero histograms + pack weights ----------------
__global__ void zero_pack(int* cnt, int* outcnt,
                          const float* __restrict__ W1, const float* __restrict__ W2,
                          uint32_t* w1h, uint32_t* w1l, uint32_t* w2h, uint32_t* w2l) {
    int i = blockIdx.x * blockDim.x + threadIdx.x;
    if (i < 3 * NNODES) { cnt[i] = 0; outcnt[i] = 0; }
    if (i < 64 * 128) {
        int kp = i >> 7, c = i & 127;
        split2(W1[(2 * kp) * FHID + c], W1[(2 * kp + 1) * FHID + c], w1h[i], w1l[i]);
    }
    if (i < 64 * 64) {
        int kp = i >> 6, c = i & 63;
        split2(W2[(2 * kp) * FOUT + c], W2[(2 * kp + 1) * FOUT + c], w2h[i], w2l[i]);
    }
}

// ---------------- launch 1: degree histograms ----------------
__global__ void hist_all(I3 srcs, I3 dsts, int* cnt, int* outcnt) {
    int g = blockIdx.y;
    int e = blockIdx.x * blockDim.x + threadIdx.x;
    if (e < NEDGES) {
        atomicAdd(&cnt   [g * NNODES + dsts.p[g][e]], 1);
        atomicAdd(&outcnt[g * NNODES + srcs.p[g][e]], 1);
    }
}

// ---------------- launch 2: scan + norms (one block per graph) ----------------
// After this kernel: rowstart = exclusive scan of in-degrees; cnt[i] = rowstart[i]
// (absolute fill cursor); nsrc/ndst = rsqrt norms.
__global__ void scan_norms(int* __restrict__ cntAll,
                           const int* __restrict__ outcntAll,
                           int* __restrict__ rowstartAll,
                           float* __restrict__ nsrcAll,
                           float* __restrict__ ndstAll) {
    __shared__ int part[1024];
    const int gb = blockIdx.x;
    int* cnt          = cntAll      + gb * NNODES;
    const int* outcnt = outcntAll   + gb * NNODES;
    int* rowstart     = rowstartAll + gb * (NNODES + 1);
    float* nsrc       = nsrcAll + gb * NNODES;
    float* ndst       = ndstAll + gb * NNODES;
    const int t = threadIdx.x;
    const int chunk = (NNODES + 1023) / 1024;
    const int lo = t * chunk;
    const int hi = min(lo + chunk, NNODES);
    int s = 0;
    for (int i = lo; i < hi; i++) {
        int c = cnt[i];
        s += c;
        ndst[i] = rsqrtf(fmaxf((float)c, 1.f));
        nsrc[i] = rsqrtf(fmaxf((float)outcnt[i], 1.f));
    }
    part[t] = s;
    __syncthreads();
    for (int off = 1; off < 1024; off <<= 1) {
        int v = (t >= off) ? part[t - off] : 0;
        __syncthreads();
        part[t] += v;
        __syncthreads();
    }
    int run = part[t] - s;
    for (int i = lo; i < hi; i++) {
        int c = cnt[i];
        rowstart[i] = run;
        cnt[i] = run;          // cursor = row start (absolute)
        run += c;
    }
    if (t == 1023) rowstart[NNODES] = part[1023];
}

// ---------------- launch 3: CSR fill (cursor-in-cnt; ncu capture slot) ----------------
__global__ void fill_all(I3 srcs, I3 dsts, int* cnt, int* __restrict__ esrcAll) {
    int g = blockIdx.y;
    int e = blockIdx.x * blockDim.x + threadIdx.x;
    if (e < NEDGES) {
        int d = dsts.p[g][e];
        int pos = atomicAdd(&cnt[g * NNODES + d], 1);   // absolute position
        esrcAll[g * NEDGES + pos] = srcs.p[g][e];
    }
}

// ---------------- launches 4-6: scaled gather SpMM, ONE GRAPH per launch ----------------
// XS[i,:] = sum_{e in row i} nsrc[s]*feat[s,:]  -> packed bf16 hi/lo planes
// Per-graph launch keeps the 51MB feature matrix L2-resident across its 16x reuse.
__global__ __launch_bounds__(256)
void spmm_scaled(const float* __restrict__ X,
                 const int* __restrict__ rowstart,
                 const int* __restrict__ esrc,
                 uint32_t* __restrict__ XSh,
                 uint32_t* __restrict__ XSl,
                 const float* __restrict__ nsrc)
{
    int gt = blockIdx.x * blockDim.x + threadIdx.x;
    int row = gt >> 5;        // warp id == row
    int lc  = gt & 31;        // float4 lane (32 x 4 = 128 cols)
    if (row >= NNODES) return;

    int beg = rowstart[row];
    int end = rowstart[row + 1];
    float4 acc = make_float4(0.f, 0.f, 0.f, 0.f);
    int e = beg;
    for (; e + 4 <= end; e += 4) {
        int s0 = __ldg(esrc + e + 0);
        int s1 = __ldg(esrc + e + 1);
        int s2 = __ldg(esrc + e + 2);
        int s3 = __ldg(esrc + e + 3);
        float w0 = __ldg(nsrc + s0), w1 = __ldg(nsrc + s1);
        float w2 = __ldg(nsrc + s2), w3 = __ldg(nsrc + s3);
        float4 v0 = __ldg((const float4*)(X + (size_t)s0 * FIN) + lc);
        float4 v1 = __ldg((const float4*)(X + (size_t)s1 * FIN) + lc);
        float4 v2 = __ldg((const float4*)(X + (size_t)s2 * FIN) + lc);
        float4 v3 = __ldg((const float4*)(X + (size_t)s3 * FIN) + lc);
        acc.x = fmaf(w0, v0.x, fmaf(w1, v1.x, fmaf(w2, v2.x, fmaf(w3, v3.x, acc.x))));
        acc.y = fmaf(w0, v0.y, fmaf(w1, v1.y, fmaf(w2, v2.y, fmaf(w3, v3.y, acc.y))));
        acc.z = fmaf(w0, v0.z, fmaf(w1, v1.z, fmaf(w2, v2.z, fmaf(w3, v3.z, acc.z))));
        acc.w = fmaf(w0, v0.w, fmaf(w1, v1.w, fmaf(w2, v2.w, fmaf(w3, v3.w, acc.w))));
    }
    for (; e < end; e++) {
        int s = __ldg(esrc + e);
        float ws = __ldg(nsrc + s);
        float4 v = __ldg((const float4*)(X + (size_t)s * FIN) + lc);
        acc.x = fmaf(ws, v.x, acc.x);
        acc.y = fmaf(ws, v.y, acc.y);
        acc.z = fmaf(ws, v.z, acc.z);
        acc.w = fmaf(ws, v.w, acc.w);
    }
    // pack to bf16 hi/lo planes (k-pair packed: word j covers cols 2j,2j+1)
    uint32_t h0, l0, h1, l1;
    split2(acc.x, acc.y, h0, l0);
    split2(acc.z, acc.w, h1, l1);
    *((uint2*)(XSh + (size_t)row * 64) + lc) = make_uint2(h0, h1);
    *((uint2*)(XSl + (size_t)row * 64) + lc) = make_uint2(l0, l1);
}

// ---------------- launch 7: fused dense chain ----------------
// H2 = relu( (XS @ W1) * ndst + b1 ) @ W2 * nsrc
#define LDAp 12
#define LDB1 136
#define LDT  68
#define LDB2 72
#define OFF_AH 0
#define OFF_AL (OFF_AH + 128 * LDAp)
#define OFF_B1H (OFF_AL + 128 * LDAp)
#define OFF_B1L (OFF_B1H + 8 * LDB1)
#define OFF_TH (OFF_B1L + 8 * LDB1)
#define OFF_TL (OFF_TH + 128 * LDT)
#define OFF_B2H (OFF_TL + 128 * LDT)
#define OFF_B2L (OFF_B2H + 8 * LDB2)
#define OFF_BSH (OFF_B2L + 8 * LDB2)
#define SMEM_WORDS (OFF_BSH + 128)

__global__ __launch_bounds__(256)
void fused_gemm(const uint32_t* __restrict__ XShBase,
                const uint32_t* __restrict__ XSlBase,
                const uint32_t* __restrict__ W1h, const uint32_t* __restrict__ W1l,
                const uint32_t* __restrict__ W2h, const uint32_t* __restrict__ W2l,
                const float* __restrict__ b1,
                float* __restrict__ H2base,
                const float* __restrict__ nsrcAll,
                const float* __restrict__ ndstAll)
{
    extern __shared__ uint32_t sm[];
    uint32_t* Ahp = sm + OFF_AH;    // [128][LDAp]
    uint32_t* Alp = sm + OFF_AL;
    uint32_t* B1h = sm + OFF_B1H;   // [8][LDB1]
    uint32_t* B1l = sm + OFF_B1L;
    uint32_t* Th  = sm + OFF_TH;    // [128][LDT]
    uint32_t* Tl  = sm + OFF_TL;
    uint32_t* B2h = sm + OFF_B2H;   // [8][LDB2]
    uint32_t* B2l = sm + OFF_B2L;
    float*    bsh = (float*)(sm + OFF_BSH);

    const int gidx = blockIdx.y;
    const uint32_t* XSh = XShBase + (size_t)gidx * NNODES * 64;
    const uint32_t* XSl = XSlBase + (size_t)gidx * NNODES * 64;
    float*       H2   = H2base + (size_t)gidx * NNODES * FOUT;
    const float* nsrc = nsrcAll + gidx * NNODES;
    const float* ndst = ndstAll + gidx * NNODES;

    const int tid  = threadIdx.x;
    const int warp = tid >> 5;
    const int lane = tid & 31;
    const int warp_m = warp & 3;
    const int warp_n = warp >> 2;
    const int m0w = warp_m * 32;
    const int g  = lane >> 2;
    const int tg = lane & 3;
    const int blockRow = blockIdx.x * 128;
    const int M = NNODES;

    if (tid < FHID) bsh[tid] = b1[tid];

    // ================= stage 1: T = XS @ W1 (3-term bf16) =================
    float acc1[2][8][4];
#pragma unroll
    for (int mi = 0; mi < 2; mi++)
#pragma unroll
        for (int ni = 0; ni < 8; ni++)
#pragma unroll
            for (int j = 0; j < 4; j++) acc1[mi][ni][j] = 0.f;

    const int n0w1 = warp_n * 64;
    const int arow = tid >> 1;          // 0..127
    const int aq   = (tid & 1) * 4;     // uint4 column within 8-wide chunk

    for (int kc = 0; kc < FIN; kc += 16) {
        __syncthreads();
        // A chunk: pre-packed planes, direct copy
        {
            int grow = blockRow + arow;
            uint4 vh = make_uint4(0u, 0u, 0u, 0u);
            uint4 vl = make_uint4(0u, 0u, 0u, 0u);
            if (grow < M) {
                vh = *(const uint4*)(XSh + (size_t)grow * 64 + kc / 2 + aq);
                vl = *(const uint4*)(XSl + (size_t)grow * 64 + kc / 2 + aq);
            }
            *(uint4*)&Ahp[arow * LDAp + aq] = vh;
            *(uint4*)&Alp[arow * LDAp + aq] = vl;
        }
        // B1 chunk (pre-packed)
        {
            int jp = tid >> 5;
            int c4 = (tid & 31) * 4;
            *(uint4*)&B1h[jp * LDB1 + c4] =
                *(const uint4*)(W1h + (size_t)(kc / 2 + jp) * FHID + c4);
            *(uint4*)&B1l[jp * LDB1 + c4] =
                *(const uint4*)(W1l + (size_t)(kc / 2 + jp) * FHID + c4);
        }
        __syncthreads();

        uint32_t ah[2][4], al[2][4];
#pragma unroll
        for (int mi = 0; mi < 2; mi++) {
            int r = m0w + mi * 16 + g;
            ah[mi][0] = Ahp[r * LDAp + tg];            al[mi][0] = Alp[r * LDAp + tg];
            ah[mi][1] = Ahp[(r + 8) * LDAp + tg];      al[mi][1] = Alp[(r + 8) * LDAp + tg];
            ah[mi][2] = Ahp[r * LDAp + tg + 4];        al[mi][2] = Alp[r * LDAp + tg + 4];
            ah[mi][3] = Ahp[(r + 8) * LDAp + tg + 4];  al[mi][3] = Alp[(r + 8) * LDAp + tg + 4];
        }
#pragma unroll
        for (int ni = 0; ni < 8; ni++) {
            int c = n0w1 + ni * 8 + g;
            uint32_t bh[2], bl[2];
            bh[0] = B1h[tg * LDB1 + c];        bl[0] = B1l[tg * LDB1 + c];
            bh[1] = B1h[(tg + 4) * LDB1 + c];  bl[1] = B1l[(tg + 4) * LDB1 + c];
#pragma unroll
            for (int mi = 0; mi < 2; mi++) {
                mma_bf16(acc1[mi][ni], al[mi], bh);
                mma_bf16(acc1[mi][ni], ah[mi], bl);
                mma_bf16(acc1[mi][ni], ah[mi], bh);
            }
        }
    }

    // ---- t = relu(T*ndst + b1), packed bf16 hi/lo into smem ----
    __syncthreads();
#pragma unroll
    for (int mi = 0; mi < 2; mi++) {
        int r0 = m0w + mi * 16 + g;
        int r1 = r0 + 8;
        int gr0 = blockRow + r0, gr1 = blockRow + r1;
        float nd0 = (gr0 < M) ? ndst[gr0] : 0.f;
        float nd1 = (gr1 < M) ? ndst[gr1] : 0.f;
#pragma unroll
        for (int ni = 0; ni < 8; ni++) {
            int col = n0w1 + ni * 8 + 2 * tg;
            int cp  = col >> 1;
            float t00 = fmaxf(fmaf(acc1[mi][ni][0], nd0, bsh[col]), 0.f);
            float t01 = fmaxf(fmaf(acc1[mi][ni][1], nd0, bsh[col + 1]), 0.f);
            float t10 = fmaxf(fmaf(acc1[mi][ni][2], nd1, bsh[col]), 0.f);
            float t11 = fmaxf(fmaf(acc1[mi][ni][3], nd1, bsh[col + 1]), 0.f);
            uint32_t h, l;
            split2(t00, t01, h, l);
            Th[r0 * LDT + cp] = h;  Tl[r0 * LDT + cp] = l;
            split2(t10, t11, h, l);
            Th[r1 * LDT + cp] = h;  Tl[r1 * LDT + cp] = l;
        }
    }

    // ================= stage 2: H2 = t @ W2 * nsrc =================
    float acc2[2][4][4];
#pragma unroll
    for (int mi = 0; mi < 2; mi++)
#pragma unroll
        for (int ni = 0; ni < 4; ni++)
#pragma unroll
            for (int j = 0; j < 4; j++) acc2[mi][ni][j] = 0.f;

    const int n0w2 = warp_n * 32;

    for (int ch = 0; ch < 8; ch++) {
        __syncthreads();
        if (tid < 128) {
            int jp = tid >> 4;
            int c4 = (tid & 15) * 4;
            *(uint4*)&B2h[jp * LDB2 + c4] =
                *(const uint4*)(W2h + (size_t)(ch * 8 + jp) * FOUT + c4);
        } else {
            int t2 = tid - 128;
            int jp = t2 >> 4;
            int c4 = (t2 & 15) * 4;
            *(uint4*)&B2l[jp * LDB2 + c4] =
                *(const uint4*)(W2l + (size_t)(ch * 8 + jp) * FOUT + c4);
        }
        __syncthreads();

        int cb = ch * 8;
        uint32_t ah[2][4], al[2][4];
#pragma unroll
        for (int mi = 0; mi < 2; mi++) {
            int r = m0w + mi * 16 + g;
            ah[mi][0] = Th[r * LDT + cb + tg];            al[mi][0] = Tl[r * LDT + cb + tg];
            ah[mi][1] = Th[(r + 8) * LDT + cb + tg];      al[mi][1] = Tl[(r + 8) * LDT + cb + tg];
            ah[mi][2] = Th[r * LDT + cb + tg + 4];        al[mi][2] = Tl[r * LDT + cb + tg + 4];
            ah[mi][3] = Th[(r + 8) * LDT + cb + tg + 4];  al[mi][3] = Tl[(r + 8) * LDT + cb + tg + 4];
        }
#pragma unroll
        for (int ni = 0; ni < 4; ni++) {
            int c = n0w2 + ni * 8 + g;
            uint32_t bh[2], bl[2];
            bh[0] = B2h[tg * LDB2 + c];        bl[0] = B2l[tg * LDB2 + c];
            bh[1] = B2h[(tg + 4) * LDB2 + c];  bl[1] = B2l[(tg + 4) * LDB2 + c];
#pragma unroll
            for (int mi = 0; mi < 2; mi++) {
                mma_bf16(acc2[mi][ni], al[mi], bh);
                mma_bf16(acc2[mi][ni], ah[mi], bl);
                mma_bf16(acc2[mi][ni], ah[mi], bh);
            }
        }
    }

    // ---- epilogue: H2 = acc2 * nsrc ----
#pragma unroll
    for (int mi = 0; mi < 2; mi++) {
        int gr0 = blockRow + m0w + mi * 16 + g;
        int gr1 = gr0 + 8;
        float s0 = (gr0 < M) ? nsrc[gr0] : 0.f;
        float s1 = (gr1 < M) ? nsrc[gr1] : 0.f;
#pragma unroll
        for (int ni = 0; ni < 4; ni++) {
            int col = n0w2 + ni * 8 + 2 * tg;
            if (gr0 < M)
                *(float2*)(H2 + (size_t)gr0 * FOUT + col) =
                    make_float2(acc2[mi][ni][0] * s0, acc2[mi][ni][1] * s0);
            if (gr1 < M)
                *(float2*)(H2 + (size_t)gr1 * FOUT + col) =
                    make_float2(acc2[mi][ni][2] * s1, acc2[mi][ni][3] * s1);
        }
    }
}

// ---------------- launch 8: final gather SpMM ----------------
__global__ __launch_bounds__(256)
void spmm_out(const float* __restrict__ H2base,
              const int* __restrict__ rowstartAll,
              const int* __restrict__ esrcAll,
              float* __restrict__ outBase,
              const float* __restrict__ ndstAll,
              const float* __restrict__ bias)
{
    constexpr int C = FOUT, C4 = C / 4, RPW = 32 / C4;   // 16 lanes/row, 2 rows/warp
    const int gidx = blockIdx.y;
    const float* H = H2base + (size_t)gidx * NNODES * C;
    const int* rowstart = rowstartAll + gidx * (NNODES + 1);
    const int* esrc = esrcAll + (size_t)gidx * NEDGES;
    float* out = outBase + (size_t)gidx * NNODES * C;

    int gt = blockIdx.x * blockDim.x + threadIdx.x;
    int w = gt >> 5;
    int lane = gt & 31;
    int sub = lane / C4;
    int lc  = lane % C4;
    int row = w * RPW + sub;
    if (row >= NNODES) return;

    int beg = rowstart[row];
    int end = rowstart[row + 1];
    float4 acc = make_float4(0.f, 0.f, 0.f, 0.f);
    int e = beg;
    for (; e + 4 <= end; e += 4) {
        int s0 = __ldg(esrc + e + 0);
        int s1 = __ldg(esrc + e + 1);
        int s2 = __ldg(esrc + e + 2);
        int s3 = __ldg(esrc + e + 3);
        float4 v0 = __ldg((const float4*)(H + (size_t)s0 * C) + lc);
        float4 v1 = __ldg((const float4*)(H + (size_t)s1 * C) + lc);
        float4 v2 = __ldg((const float4*)(H + (size_t)s2 * C) + lc);
        float4 v3 = __ldg((const float4*)(H + (size_t)s3 * C) + lc);
        acc.x += (v0.x + v1.x) + (v2.x + v3.x);
        acc.y += (v0.y + v1.y) + (v2.y + v3.y);
        acc.z += (v0.z + v1.z) + (v2.z + v3.z);
        acc.w += (v0.w + v1.w) + (v2.w + v3.w);
    }
    for (; e < end; e++) {
        int s = __ldg(esrc + e);
        float4 v = __ldg((const float4*)(H + (size_t)s * C) + lc);
        acc.x += v.x; acc.y += v.y; acc.z += v.z; acc.w += v.w;
    }
    float nd = ndstAll[gidx * NNODES + row];
    float4 b = ((const float4*)bias)[lc];
    acc.x = fmaf(acc.x, nd, b.x);
    acc.y = fmaf(acc.y, nd, b.y);
    acc.z = fmaf(acc.z, nd, b.z);
    acc.w = fmaf(acc.w, nd, b.w);
    *((float4*)(out + (size_t)row * C) + lc) = acc;
}

// ---------------- launch ----------------
extern "C" void kernel_launch(void* const* d_in, const int* in_sizes, int n_in,
                              void* d_out, int out_size)
{
    float *H2, *nsrc, *ndst;
    int *cnt, *outcnt, *rowstart, *esrc;
    uint32_t *xsh, *xsl, *w1h, *w1l, *w2h, *w2l;
    cudaGetSymbolAddress((void**)&xsh,      g_XSh);
    cudaGetSymbolAddress((void**)&xsl,      g_XSl);
    cudaGetSymbolAddress((void**)&H2,       g_H2);
    cudaGetSymbolAddress((void**)&cnt,      g_cnt);
    cudaGetSymbolAddress((void**)&outcnt,   g_outcnt);
    cudaGetSymbolAddress((void**)&rowstart, g_rowstart);
    cudaGetSymbolAddress((void**)&esrc,     g_esrc);
    cudaGetSymbolAddress((void**)&nsrc,     g_nsrc);
    cudaGetSymbolAddress((void**)&ndst,     g_ndst);
    cudaGetSymbolAddress((void**)&w1h,      g_W1h);
    cudaGetSymbolAddress((void**)&w1l,      g_W1l);
    cudaGetSymbolAddress((void**)&w2h,      g_W2h);
    cudaGetSymbolAddress((void**)&w2l,      g_W2l);

    F3 feats = {{ (const float*)d_in[0], (const float*)d_in[3], (const float*)d_in[6] }};
    I3 srcs  = {{ (const int*)d_in[1],   (const int*)d_in[4],   (const int*)d_in[7] }};
    I3 dsts  = {{ (const int*)d_in[2],   (const int*)d_in[5],   (const int*)d_in[8] }};
    const float* W1 = (const float*)d_in[9];
    const float* b1 = (const float*)d_in[10];
    const float* W2 = (const float*)d_in[11];
    const float* b2 = (const float*)d_in[12];

    static const size_t SMEM_BYTES = SMEM_WORDS * sizeof(uint32_t);
    cudaFuncSetAttribute(fused_gemm, cudaFuncAttributeMaxDynamicSharedMemorySize,
                         (int)SMEM_BYTES);

    dim3 gE((NEDGES + 255) / 256, 3);
    dim3 gG((NNODES + 127) / 128, 3);
    const int gS1 = (NNODES * 32 + 255) / 256;
    dim3 gS2((NNODES * 16 + 255) / 256, 3);

    zero_pack <<<(3 * NNODES + 255) / 256, 256>>>(cnt, outcnt, W1, W2, w1h, w1l, w2h, w2l);
    hist_all  <<<gE, 256>>>(srcs, dsts, cnt, outcnt);
    scan_norms<<<3, 1024>>>(cnt, outcnt, rowstart, nsrc, ndst);
    fill_all  <<<gE, 256>>>(srcs, dsts, cnt, esrc);      // <- ncu capture slot (idx 3)

    // XS = gather(nsrc * feat), one graph per launch (L2-resident features)
    for (int g = 0; g < 3; g++)
        spmm_scaled<<<gS1, 256>>>(feats.p[g],
                                  rowstart + g * (NNODES + 1),
                                  esrc + (size_t)g * NEDGES,
                                  xsh + (size_t)g * NNODES * 64,
                                  xsl + (size_t)g * NNODES * 64,
                                  nsrc + g * NNODES);

    // H2 = relu((XS@W1)*ndst + b1) @ W2 * nsrc
    fused_gemm<<<gG, 256, SMEM_BYTES>>>(xsh, xsl, w1h, w1l, w2h, w2l, b1, H2, nsrc, ndst);
    // out = gather(H2)*ndst + b2
    spmm_out<<<gS2, 256>>>(H2, rowstart, esrc, (float*)d_out, ndst, b2);
}

// round 9
// speedup vs baseline: 1.2927x; 1.0368x over previous
#include <cuda_runtime.h>
#include <cuda_bf16.h>
#include <cstdint>

#define NNODES 100000
#define NEDGES 1600000
#define FIN 128
#define FHID 128
#define FOUT 64

// ---------------- scratch (static device globals; no allocation) ----------------
__device__ uint32_t g_XSh[(size_t)3 * NNODES * 64];    // XS bf16-hi plane (k-pairs packed)
__device__ uint32_t g_XSl[(size_t)3 * NNODES * 64];    // XS bf16-lo plane
__device__ float    g_H2 [(size_t)3 * NNODES * FOUT];  // layer-2 transformed features
__device__ int      g_cnt     [3 * NNODES];            // cursor (holds rowstart after scan)
__device__ int      g_outcnt  [3 * NNODES];
__device__ int      g_rowstart[3 * (NNODES + 1)];
__device__ int      g_esrc    [3 * NEDGES];
__device__ float    g_nsrc    [3 * NNODES];
__device__ float    g_ndst    [3 * NNODES];
__device__ uint32_t g_W1h[64 * 128], g_W1l[64 * 128];  // W1 packed bf16 hi/lo (k-pairs)
__device__ uint32_t g_W2h[64 * 64],  g_W2l[64 * 64];   // W2 packed bf16 hi/lo

struct F3 { const float* p[3]; };
struct I3 { const int*   p[3]; };

// ---------------- bf16 split helpers ----------------
__device__ __forceinline__ void split2(float f0, float f1, uint32_t& uh, uint32_t& ul) {
    __nv_bfloat16 h0 = __float2bfloat16_rn(f0), h1 = __float2bfloat16_rn(f1);
    float r0 = f0 - __bfloat162float(h0);
    float r1 = f1 - __bfloat162float(h1);
    __nv_bfloat16 l0 = __float2bfloat16_rn(r0), l1 = __float2bfloat16_rn(r1);
    uh = ((uint32_t)(*(uint16_t*)&h1) << 16) | (uint32_t)(*(uint16_t*)&h0);
    ul = ((uint32_t)(*(uint16_t*)&l1) << 16) | (uint32_t)(*(uint16_t*)&l0);
}

__device__ __forceinline__ void mma_bf16(float* d, const uint32_t* a, const uint32_t* b) {
    asm volatile(
        "mma.sync.aligned.m16n8k16.row.col.f32.bf16.bf16.f32 "
        "{%0,%1,%2,%3},{%4,%5,%6,%7},{%8,%9},{%0,%1,%2,%3};"
        : "+f"(d[0]), "+f"(d[1]), "+f"(d[2]), "+f"(d[3])
        : "r"(a[0]), "r"(a[1]), "r"(a[2]), "r"(a[3]), "r"(b[0]), "r"(b[1]));
}

// ---------------- launch 0: zero histograms + pack weights ----------------
__global__ void zero_pack(int* cnt, int* outcnt,
                          const float* __restrict__ W1, const float* __restrict__ W2,
                          uint32_t* w1h, uint32_t* w1l, uint32_t* w2h, uint32_t* w2l) {
    int i = blockIdx.x * blockDim.x + threadIdx.x;
    if (i < 3 * NNODES) { cnt[i] = 0; outcnt[i] = 0; }
    if (i < 64 * 128) {
        int kp = i >> 7, c = i & 127;
        split2(W1[(2 * kp) * FHID + c], W1[(2 * kp + 1) * FHID + c], w1h[i], w1l[i]);
    }
    if (i < 64 * 64) {
        int kp = i >> 6, c = i & 63;
        split2(W2[(2 * kp) * FOUT + c], W2[(2 * kp + 1) * FOUT + c], w2h[i], w2l[i]);
    }
}

// ---------------- launch 1: degree histograms (4 edges/thread, int4 loads) ----------------
__global__ __launch_bounds__(256)
void hist_all(I3 srcs, I3 dsts, int* cnt, int* outcnt) {
    int g = blockIdx.y;
    int i = blockIdx.x * blockDim.x + threadIdx.x;
    if (i < NEDGES / 4) {
        int4 d4 = __ldg((const int4*)dsts.p[g] + i);
        int4 s4 = __ldg((const int4*)srcs.p[g] + i);
        int* c = cnt + g * NNODES;
        int* o = outcnt + g * NNODES;
        atomicAdd(c + d4.x, 1);
        atomicAdd(c + d4.y, 1);
        atomicAdd(c + d4.z, 1);
        atomicAdd(c + d4.w, 1);
        atomicAdd(o + s4.x, 1);
        atomicAdd(o + s4.y, 1);
        atomicAdd(o + s4.z, 1);
        atomicAdd(o + s4.w, 1);
    }
}

// ---------------- launch 2: scan + norms (one block per graph) ----------------
// After: rowstart = exclusive scan of in-degrees; cnt[i] = rowstart[i] (cursor);
// nsrc/ndst = rsqrt norms.
__global__ void scan_norms(int* __restrict__ cntAll,
                           const int* __restrict__ outcntAll,
                           int* __restrict__ rowstartAll,
                           float* __restrict__ nsrcAll,
                           float* __restrict__ ndstAll) {
    __shared__ int part[1024];
    const int gb = blockIdx.x;
    int* cnt          = cntAll      + gb * NNODES;
    const int* outcnt = outcntAll   + gb * NNODES;
    int* rowstart     = rowstartAll + gb * (NNODES + 1);
    float* nsrc       = nsrcAll + gb * NNODES;
    float* ndst       = ndstAll + gb * NNODES;
    const int t = threadIdx.x;
    const int chunk = (NNODES + 1023) / 1024;
    const int lo = t * chunk;
    const int hi = min(lo + chunk, NNODES);
    int s = 0;
    for (int i = lo; i < hi; i++) {
        int c = cnt[i];
        s += c;
        ndst[i] = rsqrtf(fmaxf((float)c, 1.f));
        nsrc[i] = rsqrtf(fmaxf((float)outcnt[i], 1.f));
    }
    part[t] = s;
    __syncthreads();
    for (int off = 1; off < 1024; off <<= 1) {
        int v = (t >= off) ? part[t - off] : 0;
        __syncthreads();
        part[t] += v;
        __syncthreads();
    }
    int run = part[t] - s;
    for (int i = lo; i < hi; i++) {
        int c = cnt[i];
        rowstart[i] = run;
        cnt[i] = run;          // cursor = row start (absolute)
        run += c;
    }
    if (t == 1023) rowstart[NNODES] = part[1023];
}

// ---------------- launch 3: CSR fill (4 edges/thread; ncu capture slot) ----------------
__global__ __launch_bounds__(256)
void fill_all(I3 srcs, I3 dsts, int* cnt, int* __restrict__ esrcAll) {
    int g = blockIdx.y;
    int i = blockIdx.x * blockDim.x + threadIdx.x;
    if (i < NEDGES / 4) {
        int4 d4 = __ldg((const int4*)dsts.p[g] + i);
        int4 s4 = __ldg((const int4*)srcs.p[g] + i);
        int* c = cnt + g * NNODES;
        int* esrc = esrcAll + (size_t)g * NEDGES;
        // 4 independent atomic->store chains (MLP=4 over ATOMG latency)
        int p0 = atomicAdd(c + d4.x, 1);
        int p1 = atomicAdd(c + d4.y, 1);
        int p2 = atomicAdd(c + d4.z, 1);
        int p3 = atomicAdd(c + d4.w, 1);
        esrc[p0] = s4.x;
        esrc[p1] = s4.y;
        esrc[p2] = s4.z;
        esrc[p3] = s4.w;
    }
}

// ---------------- launches 4-6: scaled gather SpMM, ONE GRAPH per launch ----------------
// XS[i,:] = sum_{e in row i} nsrc[s]*feat[s,:]  -> packed bf16 hi/lo planes
__global__ __launch_bounds__(256)
void spmm_scaled(const float* __restrict__ X,
                 const int* __restrict__ rowstart,
                 const int* __restrict__ esrc,
                 uint32_t* __restrict__ XSh,
                 uint32_t* __restrict__ XSl,
                 const float* __restrict__ nsrc)
{
    int gt = blockIdx.x * blockDim.x + threadIdx.x;
    int row = gt >> 5;        // warp id == row
    int lc  = gt & 31;        // float4 lane (32 x 4 = 128 cols)
    if (row >= NNODES) return;

    int beg = rowstart[row];
    int end = rowstart[row + 1];
    float4 acc = make_float4(0.f, 0.f, 0.f, 0.f);
    int e = beg;
    for (; e + 4 <= end; e += 4) {
        int s0 = __ldg(esrc + e + 0);
        int s1 = __ldg(esrc + e + 1);
        int s2 = __ldg(esrc + e + 2);
        int s3 = __ldg(esrc + e + 3);
        float w0 = __ldg(nsrc + s0), w1 = __ldg(nsrc + s1);
        float w2 = __ldg(nsrc + s2), w3 = __ldg(nsrc + s3);
        float4 v0 = __ldg((const float4*)(X + (size_t)s0 * FIN) + lc);
        float4 v1 = __ldg((const float4*)(X + (size_t)s1 * FIN) + lc);
        float4 v2 = __ldg((const float4*)(X + (size_t)s2 * FIN) + lc);
        float4 v3 = __ldg((const float4*)(X + (size_t)s3 * FIN) + lc);
        acc.x = fmaf(w0, v0.x, fmaf(w1, v1.x, fmaf(w2, v2.x, fmaf(w3, v3.x, acc.x))));
        acc.y = fmaf(w0, v0.y, fmaf(w1, v1.y, fmaf(w2, v2.y, fmaf(w3, v3.y, acc.y))));
        acc.z = fmaf(w0, v0.z, fmaf(w1, v1.z, fmaf(w2, v2.z, fmaf(w3, v3.z, acc.z))));
        acc.w = fmaf(w0, v0.w, fmaf(w1, v1.w, fmaf(w2, v2.w, fmaf(w3, v3.w, acc.w))));
    }
    for (; e < end; e++) {
        int s = __ldg(esrc + e);
        float ws = __ldg(nsrc + s);
        float4 v = __ldg((const float4*)(X + (size_t)s * FIN) + lc);
        acc.x = fmaf(ws, v.x, acc.x);
        acc.y = fmaf(ws, v.y, acc.y);
        acc.z = fmaf(ws, v.z, acc.z);
        acc.w = fmaf(ws, v.w, acc.w);
    }
    uint32_t h0, l0, h1, l1;
    split2(acc.x, acc.y, h0, l0);
    split2(acc.z, acc.w, h1, l1);
    *((uint2*)(XSh + (size_t)row * 64) + lc) = make_uint2(h0, h1);
    *((uint2*)(XSl + (size_t)row * 64) + lc) = make_uint2(l0, l1);
}

// ---------------- launch 7: fused dense chain ----------------
// H2 = relu( (XS @ W1) * ndst + b1 ) @ W2 * nsrc
#define LDAp 12
#define LDB1 136
#define LDT  68
#define LDB2 72
#define OFF_AH 0
#define OFF_AL (OFF_AH + 128 * LDAp)
#define OFF_B1H (OFF_AL + 128 * LDAp)
#define OFF_B1L (OFF_B1H + 8 * LDB1)
#define OFF_TH (OFF_B1L + 8 * LDB1)
#define OFF_TL (OFF_TH + 128 * LDT)
#define OFF_B2H (OFF_TL + 128 * LDT)
#define OFF_B2L (OFF_B2H + 8 * LDB2)
#define OFF_BSH (OFF_B2L + 8 * LDB2)
#define SMEM_WORDS (OFF_BSH + 128)

__global__ __launch_bounds__(256)
void fused_gemm(const uint32_t* __restrict__ XShBase,
                const uint32_t* __restrict__ XSlBase,
                const uint32_t* __restrict__ W1h, const uint32_t* __restrict__ W1l,
                const uint32_t* __restrict__ W2h, const uint32_t* __restrict__ W2l,
                const float* __restrict__ b1,
                float* __restrict__ H2base,
                const float* __restrict__ nsrcAll,
                const float* __restrict__ ndstAll)
{
    extern __shared__ uint32_t sm[];
    uint32_t* Ahp = sm + OFF_AH;    // [128][LDAp]
    uint32_t* Alp = sm + OFF_AL;
    uint32_t* B1h = sm + OFF_B1H;   // [8][LDB1]
    uint32_t* B1l = sm + OFF_B1L;
    uint32_t* Th  = sm + OFF_TH;    // [128][LDT]
    uint32_t* Tl  = sm + OFF_TL;
    uint32_t* B2h = sm + OFF_B2H;   // [8][LDB2]
    uint32_t* B2l = sm + OFF_B2L;
    float*    bsh = (float*)(sm + OFF_BSH);

    const int gidx = blockIdx.y;
    const uint32_t* XSh = XShBase + (size_t)gidx * NNODES * 64;
    const uint32_t* XSl = XSlBase + (size_t)gidx * NNODES * 64;
    float*       H2   = H2base + (size_t)gidx * NNODES * FOUT;
    const float* nsrc = nsrcAll + gidx * NNODES;
    const float* ndst = ndstAll + gidx * NNODES;

    const int tid  = threadIdx.x;
    const int warp = tid >> 5;
    const int lane = tid & 31;
    const int warp_m = warp & 3;
    const int warp_n = warp >> 2;
    const int m0w = warp_m * 32;
    const int g  = lane >> 2;
    const int tg = lane & 3;
    const int blockRow = blockIdx.x * 128;
    const int M = NNODES;

    if (tid < FHID) bsh[tid] = b1[tid];

    // ================= stage 1: T = XS @ W1 (3-term bf16) =================
    float acc1[2][8][4];
#pragma unroll
    for (int mi = 0; mi < 2; mi++)
#pragma unroll
        for (int ni = 0; ni < 8; ni++)
#pragma unroll
            for (int j = 0; j < 4; j++) acc1[mi][ni][j] = 0.f;

    const int n0w1 = warp_n * 64;
    const int arow = tid >> 1;          // 0..127
    const int aq   = (tid & 1) * 4;     // uint4 column within 8-wide chunk

    for (int kc = 0; kc < FIN; kc += 16) {
        __syncthreads();
        // A chunk: pre-packed planes, direct copy
        {
            int grow = blockRow + arow;
            uint4 vh = make_uint4(0u, 0u, 0u, 0u);
            uint4 vl = make_uint4(0u, 0u, 0u, 0u);
            if (grow < M) {
                vh = *(const uint4*)(XSh + (size_t)grow * 64 + kc / 2 + aq);
                vl = *(const uint4*)(XSl + (size_t)grow * 64 + kc / 2 + aq);
            }
            *(uint4*)&Ahp[arow * LDAp + aq] = vh;
            *(uint4*)&Alp[arow * LDAp + aq] = vl;
        }
        // B1 chunk (pre-packed)
        {
            int jp = tid >> 5;
            int c4 = (tid & 31) * 4;
            *(uint4*)&B1h[jp * LDB1 + c4] =
                *(const uint4*)(W1h + (size_t)(kc / 2 + jp) * FHID + c4);
            *(uint4*)&B1l[jp * LDB1 + c4] =
                *(const uint4*)(W1l + (size_t)(kc / 2 + jp) * FHID + c4);
        }
        __syncthreads();

        uint32_t ah[2][4], al[2][4];
#pragma unroll
        for (int mi = 0; mi < 2; mi++) {
            int r = m0w + mi * 16 + g;
            ah[mi][0] = Ahp[r * LDAp + tg];            al[mi][0] = Alp[r * LDAp + tg];
            ah[mi][1] = Ahp[(r + 8) * LDAp + tg];      al[mi][1] = Alp[(r + 8) * LDAp + tg];
            ah[mi][2] = Ahp[r * LDAp + tg + 4];        al[mi][2] = Alp[r * LDAp + tg + 4];
            ah[mi][3] = Ahp[(r + 8) * LDAp + tg + 4];  al[mi][3] = Alp[(r + 8) * LDAp + tg + 4];
        }
#pragma unroll
        for (int ni = 0; ni < 8; ni++) {
            int c = n0w1 + ni * 8 + g;
            uint32_t bh[2], bl[2];
            bh[0] = B1h[tg * LDB1 + c];        bl[0] = B1l[tg * LDB1 + c];
            bh[1] = B1h[(tg + 4) * LDB1 + c];  bl[1] = B1l[(tg + 4) * LDB1 + c];
#pragma unroll
            for (int mi = 0; mi < 2; mi++) {
                mma_bf16(acc1[mi][ni], al[mi], bh);
                mma_bf16(acc1[mi][ni], ah[mi], bl);
                mma_bf16(acc1[mi][ni], ah[mi], bh);
            }
        }
    }

    // ---- t = relu(T*ndst + b1), packed bf16 hi/lo into smem ----
    __syncthreads();
#pragma unroll
    for (int mi = 0; mi < 2; mi++) {
        int r0 = m0w + mi * 16 + g;
        int r1 = r0 + 8;
        int gr0 = blockRow + r0, gr1 = blockRow + r1;
        float nd0 = (gr0 < M) ? ndst[gr0] : 0.f;
        float nd1 = (gr1 < M) ? ndst[gr1] : 0.f;
#pragma unroll
        for (int ni = 0; ni < 8; ni++) {
            int col = n0w1 + ni * 8 + 2 * tg;
            int cp  = col >> 1;
            float t00 = fmaxf(fmaf(acc1[mi][ni][0], nd0, bsh[col]), 0.f);
            float t01 = fmaxf(fmaf(acc1[mi][ni][1], nd0, bsh[col + 1]), 0.f);
            float t10 = fmaxf(fmaf(acc1[mi][ni][2], nd1, bsh[col]), 0.f);
            float t11 = fmaxf(fmaf(acc1[mi][ni][3], nd1, bsh[col + 1]), 0.f);
            uint32_t h, l;
            split2(t00, t01, h, l);
            Th[r0 * LDT + cp] = h;  Tl[r0 * LDT + cp] = l;
            split2(t10, t11, h, l);
            Th[r1 * LDT + cp] = h;  Tl[r1 * LDT + cp] = l;
        }
    }

    // ================= stage 2: H2 = t @ W2 * nsrc =================
    float acc2[2][4][4];
#pragma unroll
    for (int mi = 0; mi < 2; mi++)
#pragma unroll
        for (int ni = 0; ni < 4; ni++)
#pragma unroll
            for (int j = 0; j < 4; j++) acc2[mi][ni][j] = 0.f;

    const int n0w2 = warp_n * 32;

    for (int ch = 0; ch < 8; ch++) {
        __syncthreads();
        if (tid < 128) {
            int jp = tid >> 4;
            int c4 = (tid & 15) * 4;
            *(uint4*)&B2h[jp * LDB2 + c4] =
                *(const uint4*)(W2h + (size_t)(ch * 8 + jp) * FOUT + c4);
        } else {
            int t2 = tid - 128;
            int jp = t2 >> 4;
            int c4 = (t2 & 15) * 4;
            *(uint4*)&B2l[jp * LDB2 + c4] =
                *(const uint4*)(W2l + (size_t)(ch * 8 + jp) * FOUT + c4);
        }
        __syncthreads();

        int cb = ch * 8;
        uint32_t ah[2][4], al[2][4];
#pragma unroll
        for (int mi = 0; mi < 2; mi++) {
            int r = m0w + mi * 16 + g;
            ah[mi][0] = Th[r * LDT + cb + tg];            al[mi][0] = Tl[r * LDT + cb + tg];
            ah[mi][1] = Th[(r + 8) * LDT + cb + tg];      al[mi][1] = Tl[(r + 8) * LDT + cb + tg];
            ah[mi][2] = Th[r * LDT + cb + tg + 4];        al[mi][2] = Tl[r * LDT + cb + tg + 4];
            ah[mi][3] = Th[(r + 8) * LDT + cb + tg + 4];  al[mi][3] = Tl[(r + 8) * LDT + cb + tg + 4];
        }
#pragma unroll
        for (int ni = 0; ni < 4; ni++) {
            int c = n0w2 + ni * 8 + g;
            uint32_t bh[2], bl[2];
            bh[0] = B2h[tg * LDB2 + c];        bl[0] = B2l[tg * LDB2 + c];
            bh[1] = B2h[(tg + 4) * LDB2 + c];  bl[1] = B2l[(tg + 4) * LDB2 + c];
#pragma unroll
            for (int mi = 0; mi < 2; mi++) {
                mma_bf16(acc2[mi][ni], al[mi], bh);
                mma_bf16(acc2[mi][ni], ah[mi], bl);
                mma_bf16(acc2[mi][ni], ah[mi], bh);
            }
        }
    }

    // ---- epilogue: H2 = acc2 * nsrc ----
#pragma unroll
    for (int mi = 0; mi < 2; mi++) {
        int gr0 = blockRow + m0w + mi * 16 + g;
        int gr1 = gr0 + 8;
        float s0 = (gr0 < M) ? nsrc[gr0] : 0.f;
        float s1 = (gr1 < M) ? nsrc[gr1] : 0.f;
#pragma unroll
        for (int ni = 0; ni < 4; ni++) {
            int col = n0w2 + ni * 8 + 2 * tg;
            if (gr0 < M)
                *(float2*)(H2 + (size_t)gr0 * FOUT + col) =
                    make_float2(acc2[mi][ni][0] * s0, acc2[mi][ni][1] * s0);
            if (gr1 < M)
                *(float2*)(H2 + (size_t)gr1 * FOUT + col) =
                    make_float2(acc2[mi][ni][2] * s1, acc2[mi][ni][3] * s1);
        }
    }
}

// ---------------- launch 8: final gather SpMM ----------------
__global__ __launch_bounds__(256)
void spmm_out(const float* __restrict__ H2base,
              const int* __restrict__ rowstartAll,
              const int* __restrict__ esrcAll,
              float* __restrict__ outBase,
              const float* __restrict__ ndstAll,
              const float* __restrict__ bias)
{
    constexpr int C = FOUT, C4 = C / 4, RPW = 32 / C4;   // 16 lanes/row, 2 rows/warp
    const int gidx = blockIdx.y;
    const float* H = H2base + (size_t)gidx * NNODES * C;
    const int* rowstart = rowstartAll + gidx * (NNODES + 1);
    const int* esrc = esrcAll + (size_t)gidx * NEDGES;
    float* out = outBase + (size_t)gidx * NNODES * C;

    int gt = blockIdx.x * blockDim.x + threadIdx.x;
    int w = gt >> 5;
    int lane = gt & 31;
    int sub = lane / C4;
    int lc  = lane % C4;
    int row = w * RPW + sub;
    if (row >= NNODES) return;

    int beg = rowstart[row];
    int end = rowstart[row + 1];
    float4 acc = make_float4(0.f, 0.f, 0.f, 0.f);
    int e = beg;
    for (; e + 4 <= end; e += 4) {
        int s0 = __ldg(esrc + e + 0);
        int s1 = __ldg(esrc + e + 1);
        int s2 = __ldg(esrc + e + 2);
        int s3 = __ldg(esrc + e + 3);
        float4 v0 = __ldg((const float4*)(H + (size_t)s0 * C) + lc);
        float4 v1 = __ldg((const float4*)(H + (size_t)s1 * C) + lc);
        float4 v2 = __ldg((const float4*)(H + (size_t)s2 * C) + lc);
        float4 v3 = __ldg((const float4*)(H + (size_t)s3 * C) + lc);
        acc.x += (v0.x + v1.x) + (v2.x + v3.x);
        acc.y += (v0.y + v1.y) + (v2.y + v3.y);
        acc.z += (v0.z + v1.z) + (v2.z + v3.z);
        acc.w += (v0.w + v1.w) + (v2.w + v3.w);
    }
    for (; e < end; e++) {
        int s = __ldg(esrc + e);
        float4 v = __ldg((const float4*)(H + (size_t)s * C) + lc);
        acc.x += v.x; acc.y += v.y; acc.z += v.z; acc.w += v.w;
    }
    float nd = ndstAll[gidx * NNODES + row];
    float4 b = ((const float4*)bias)[lc];
    acc.x = fmaf(acc.x, nd, b.x);
    acc.y = fmaf(acc.y, nd, b.y);
    acc.z = fmaf(acc.z, nd, b.z);
    acc.w = fmaf(acc.w, nd, b.w);
    *((float4*)(out + (size_t)row * C) + lc) = acc;
}

// ---------------- launch ----------------
extern "C" void kernel_launch(void* const* d_in, const int* in_sizes, int n_in,
                              void* d_out, int out_size)
{
    float *H2, *nsrc, *ndst;
    int *cnt, *outcnt, *rowstart, *esrc;
    uint32_t *xsh, *xsl, *w1h, *w1l, *w2h, *w2l;
    cudaGetSymbolAddress((void**)&xsh,      g_XSh);
    cudaGetSymbolAddress((void**)&xsl,      g_XSl);
    cudaGetSymbolAddress((void**)&H2,       g_H2);
    cudaGetSymbolAddress((void**)&cnt,      g_cnt);
    cudaGetSymbolAddress((void**)&outcnt,   g_outcnt);
    cudaGetSymbolAddress((void**)&rowstart, g_rowstart);
    cudaGetSymbolAddress((void**)&esrc,     g_esrc);
    cudaGetSymbolAddress((void**)&nsrc,     g_nsrc);
    cudaGetSymbolAddress((void**)&ndst,     g_ndst);
    cudaGetSymbolAddress((void**)&w1h,      g_W1h);
    cudaGetSymbolAddress((void**)&w1l,      g_W1l);
    cudaGetSymbolAddress((void**)&w2h,      g_W2h);
    cudaGetSymbolAddress((void**)&w2l,      g_W2l);

    F3 feats = {{ (const float*)d_in[0], (const float*)d_in[3], (const float*)d_in[6] }};
    I3 srcs  = {{ (const int*)d_in[1],   (const int*)d_in[4],   (const int*)d_in[7] }};
    I3 dsts  = {{ (const int*)d_in[2],   (const int*)d_in[5],   (const int*)d_in[8] }};
    const float* W1 = (const float*)d_in[9];
    const float* b1 = (const float*)d_in[10];
    const float* W2 = (const float*)d_in[11];
    const float* b2 = (const float*)d_in[12];

    static const size_t SMEM_BYTES = SMEM_WORDS * sizeof(uint32_t);
    cudaFuncSetAttribute(fused_gemm, cudaFuncAttributeMaxDynamicSharedMemorySize,
                         (int)SMEM_BYTES);

    dim3 gE((NEDGES / 4 + 255) / 256, 3);        // 4 edges per thread
    dim3 gG((NNODES + 127) / 128, 3);
    const int gS1 = (NNODES * 32 + 255) / 256;
    dim3 gS2((NNODES * 16 + 255) / 256, 3);

    zero_pack <<<(3 * NNODES + 255) / 256, 256>>>(cnt, outcnt, W1, W2, w1h, w1l, w2h, w2l);
    hist_all  <<<gE, 256>>>(srcs, dsts, cnt, outcnt);
    scan_norms<<<3, 1024>>>(cnt, outcnt, rowstart, nsrc, ndst);
    fill_all  <<<gE, 256>>>(srcs, dsts, cnt, esrc);      // <- ncu capture slot (idx 3)

    // XS = gather(nsrc * feat), one graph per launch (L2-resident features)
    for (int g = 0; g < 3; g++)
        spmm_scaled<<<gS1, 256>>>(feats.p[g],
                                  rowstart + g * (NNODES + 1),
                                  esrc + (size_t)g * NEDGES,
                                  xsh + (size_t)g * NNODES * 64,
                                  xsl + (size_t)g * NNODES * 64,
                                  nsrc + g * NNODES);

    // H2 = relu((XS@W1)*ndst + b1) @ W2 * nsrc
    fused_gemm<<<gG, 256, SMEM_BYTES>>>(xsh, xsl, w1h, w1l, w2h, w2l, b1, H2, nsrc, ndst);
    // out = gather(H2)*ndst + b2
    spmm_out<<<gS2, 256>>>(H2, rowstart, esrc, (float*)d_out, ndst, b2);
}